// round 6
// baseline (speedup 1.0000x reference)
#include <cuda_runtime.h>

// Not-a-knot cubic spline upsample, B x 8192 fp32 -> B x (8192*4) fp32.
// [1,4,1] tridiagonal inverse = exponential Green's function (lam = sqrt(3)-2)
// composed with the 6*[1,-2,1] rhs into a 17-tap FIR on y -> M is LOCAL.
// Persistent CTAs (6/SM), 1024-knot tiles, 256 threads, (y,M) interleaved as
// float2 in smem so eval does 3 LDS.64 + selects + 3 FMA per 4 outputs.

#define W_DIM  8192
#define NTHR   256
#define TILE_I 1024
#define KT     8
#define SYN    1056      // y slice capacity  (1024 + 32 halo)
#define SMN    1028      // (y,M) pair capacity: knots [kbase-1, kbase+1026]

#define LAM   (-0.26794919243112270647f)   // sqrt(3) - 2
#define ACOEF (0.28867513459481288225f)    // 1 / (2*sqrt(3))

__global__ __launch_bounds__(NTHR, 6)
void spline_kernel(const float* __restrict__ x, float* __restrict__ out,
                   int nout, float step, int ntiles) {
    __shared__ float  sy[SYN];
    __shared__ float2 sYM[SMN];

    const int tid = threadIdx.x;
    const int n = W_DIM - 4;

    for (int tt = blockIdx.x; tt < ntiles; tt += gridDim.x) {
        const int row = tt >> 3;                     // 8 tiles per row
        const int kbase = (tt & 7) * TILE_I;
        const float* xr = x + (size_t)row * W_DIM;
        float* outr = out + (size_t)row * nout + kbase * 4;

        const int ilo = (kbase >= 16) ? (kbase - 16) : 0;
        int ihi = kbase + TILE_I + 16; if (ihi > W_DIM) ihi = W_DIM;
        const int NY = ihi - ilo;

        __syncthreads();                             // prev tile fully consumed
        {
            const float4* x4 = (const float4*)(xr + ilo);
            float4* sy4 = (float4*)sy;
            for (int v = tid; v < (NY >> 2); v += NTHR) sy4[v] = x4[v];
        }
        __syncthreads();

        // ---- interior M via 17-tap FIR; write (y, M) pairs ----
        {
            const float C0 = -4.3923048f;
            const float C[KT] = { 2.7846097f, -0.7461340f, 0.1999261f, -0.0535701f,
                                  0.0143541f, -0.0038462f, 0.0010306f, -0.0002761f };
            int gfirst = kbase - 1; if (gfirst < 20) gfirst = 20;
            int glast = kbase + TILE_I + 1; if (glast > W_DIM - 21) glast = W_DIM - 21;
            const int lstart = ((gfirst - ilo) >> 2) << 2;   // >= 8, 4-aligned
            const int nch = ((glast - ilo - lstart) >> 2) + 1;
            for (int c = tid; c < nch; c += NTHR) {
                const int li0 = lstart + 4 * c;
                float win[20];                       // y[li0-8 .. li0+11]
                const float4* ws = (const float4*)(sy + li0 - 8);
                #pragma unroll
                for (int v = 0; v < 5; ++v) ((float4*)win)[v] = ws[v];
                #pragma unroll
                for (int m = 0; m < 4; ++m) {
                    float acc = C0 * win[8 + m];
                    #pragma unroll
                    for (int k = 1; k <= KT; ++k)
                        acc = fmaf(C[k - 1], win[8 + m - k] + win[8 + m + k], acc);
                    const int gi = ilo + li0 + m;
                    if (gi >= gfirst && gi <= glast)
                        sYM[gi - kbase + 1] = make_float2(win[8 + m], acc);
                }
            }
        }

        // ---- left edge (row-start tile): exact M[0..19] via Green sums ----
        if (kbase == 0 && tid < 20) {
            const float M1 = sy[2] - 2.f * sy[1] + sy[0];
            float SL = 0.f, lp = LAM;
            #pragma unroll 4
            for (int j = 0; j < 24; ++j) {
                float b = 6.f * (sy[j + 3] - 2.f * sy[j + 2] + sy[j + 1]);
                if (j == 0) b -= M1;
                SL = fmaf(lp, b, SL);
                lp *= LAM;
            }
            float Mv;
            if (tid == 1) {
                Mv = M1;
            } else {
                const int jj = (tid == 0) ? 0 : tid - 2;
                float acc = 0.f, p = 1.f;
                #pragma unroll 4
                for (int d = 0; d <= 12; ++d) {
                    const int j = jj - d;
                    if (j >= 0) {
                        float b = 6.f * (sy[j + 3] - 2.f * sy[j + 2] + sy[j + 1]);
                        if (j == 0) b -= M1;
                        acc = fmaf(p, b, acc);
                    }
                    p *= LAM;
                }
                p = LAM;
                #pragma unroll 4
                for (int d = 1; d <= 12; ++d) {
                    const int j = jj + d;            // always < n
                    float b = 6.f * (sy[j + 3] - 2.f * sy[j + 2] + sy[j + 1]);
                    acc = fmaf(p, b, acc);
                    p *= LAM;
                }
                float pw = LAM;                      // lam^{jj+1}
                for (int s = 0; s < jj; ++s) pw *= LAM;
                acc -= pw * SL;
                Mv = ACOEF * acc;
                if (tid == 0) Mv = 2.f * M1 - Mv;
            }
            sYM[tid + 1] = make_float2(sy[tid], Mv); // gi = tid, kbase = 0
        }

        // ---- right edge (row-end tile): exact M[W-20..W-1] ----
        if (kbase + TILE_I == W_DIM && tid >= 32 && tid < 52) {
            const int t = tid - 32;
            const int gi = W_DIM - 20 + t;
            const int lW = W_DIM - ilo;
            const float Mn2 = sy[lW - 1] - 2.f * sy[lW - 2] + sy[lW - 3];
            float SR = 0.f, lp = LAM;
            #pragma unroll 4
            for (int m = 0; m < 24; ++m) {
                const int j = n - 1 - m;
                float b = 6.f * (sy[j + 3 - ilo] - 2.f * sy[j + 2 - ilo] + sy[j + 1 - ilo]);
                if (j == n - 1) b -= Mn2;
                SR = fmaf(lp, b, SR);
                lp *= LAM;
            }
            float Mv;
            if (t == 18) {
                Mv = Mn2;                            // gi == W-2
            } else {
                const int jj = (t == 19) ? (n - 1) : (gi - 2);
                float acc = 0.f, p = 1.f;
                #pragma unroll 4
                for (int d = 0; d <= 12; ++d) {
                    const int j = jj - d;            // always >= 0
                    float b = 6.f * (sy[j + 3 - ilo] - 2.f * sy[j + 2 - ilo] + sy[j + 1 - ilo]);
                    if (j == n - 1) b -= Mn2;
                    acc = fmaf(p, b, acc);
                    p *= LAM;
                }
                p = LAM;
                #pragma unroll 4
                for (int d = 1; d <= 12; ++d) {
                    const int j = jj + d;
                    if (j < n) {
                        float b = 6.f * (sy[j + 3 - ilo] - 2.f * sy[j + 2 - ilo] + sy[j + 1 - ilo]);
                        acc = fmaf(p, b, acc);
                    }
                    p *= LAM;
                }
                float pw = LAM;                      // lam^{n-jj}
                for (int s = 0; s < n - 1 - jj; ++s) pw *= LAM;
                acc -= pw * SR;
                Mv = ACOEF * acc;
                if (t == 19) Mv = 2.f * Mn2 - Mv;
            }
            sYM[gi - kbase + 1] = make_float2(sy[gi - ilo], Mv);
        }
        __syncthreads();

        // ---- evaluate: 4 chunks/thread, 3 LDS.64 + selects + 3 FMA x4 ----
        {
            float4* out4 = (float4*)outr;
            #pragma unroll
            for (int k = 0; k < TILE_I / NTHR; ++k) {
                const int cl = tid + k * NTHR;
                const int cg = kbase + cl;
                const float q0f = (float)(4 * cg);
                const float fq0 = q0f * step;        // == reference xq
                int i0 = (int)fq0;
                if (i0 > W_DIM - 2) i0 = W_DIM - 2;
                const float fi0 = (float)i0;
                const int iL = i0 - kbase + 1;       // in [0, 1023+2]

                const float2 p0 = sYM[iL];
                const float2 p1 = sYM[iL + 1];
                const float2 p2 = sYM[iL + 2];       // may be stale; select-discarded
                const float y0 = p0.x, m0 = p0.y;
                const float y1 = p1.x, m1 = p1.y;
                const float y2 = p2.x, m2 = p2.y;

                const float Ax = y0;
                const float Ay = fmaf(fmaf(2.f, m0, m1), -(1.f / 6.f), y1 - y0);
                const float Az = 0.5f * m0;
                const float Aw = (m1 - m0) * (1.f / 6.f);
                const float Bx = y1;
                const float By = fmaf(fmaf(2.f, m1, m2), -(1.f / 6.f), y2 - y1);
                const float Bz = 0.5f * m1;
                const float Bw = (m2 - m1) * (1.f / 6.f);
                const bool bval = (i0 < W_DIM - 2);

                float4 r;
                {
                    const float u = fq0 - fi0;       // Sterbenz-exact == ref t
                    r.x = fmaf(u, fmaf(u, fmaf(u, Aw, Az), Ay), Ax);
                }
                #pragma unroll
                for (int m = 1; m < 4; ++m) {
                    const float fq = (q0f + (float)m) * step;
                    const float u = fq - fi0;        // in [0, 2), exact
                    const bool up = (u >= 1.0f) && bval;
                    const float t = up ? (u - 1.0f) : u;
                    const float cx = up ? Bx : Ax;
                    const float cy = up ? By : Ay;
                    const float cz = up ? Bz : Az;
                    const float cw = up ? Bw : Aw;
                    ((float*)&r)[m] = fmaf(t, fmaf(t, fmaf(t, cw, cz), cy), cx);
                }
                out4[cl] = r;
            }
        }
    }
}

extern "C" void kernel_launch(void* const* d_in, const int* in_sizes, int n_in,
                              void* d_out, int out_size) {
    const float* x = (const float*)d_in[0];
    float* out = (float*)d_out;

    const int B = in_sizes[0] / W_DIM;               // 512
    const int nout = out_size / B;                   // 32768
    const float step = (float)((double)(W_DIM - 1) / (double)(nout - 1));
    const int ntiles = B * (W_DIM / TILE_I);         // 4096

    int grid = 148 * 6;                              // persistent: 6 CTAs/SM
    if (grid > ntiles) grid = ntiles;
    spline_kernel<<<grid, NTHR>>>(x, out, nout, step, ntiles);
}

// round 7
// speedup vs baseline: 1.2016x; 1.2016x over previous
#include <cuda_runtime.h>

// Not-a-knot cubic spline upsample, B x 8192 fp32 -> B x (8192*4) fp32.
// [1,4,1] tridiagonal inverse = exponential Green's function (lam = sqrt(3)-2)
// composed with the 6*[1,-2,1] rhs into a 17-tap FIR on y -> M is LOCAL.
// R5 skeleton (one-shot 1024-knot tiles, 256 thr, 2 barriers, 6 CTAs/SM) +
// (y,M) interleaved as float2 so eval does 3 LDS.64 + selects + 3 FMA per
// 4 outputs.

#define W_DIM  8192
#define NTHR   256
#define TILE_I 1024
#define KT     8
#define SYN    1056      // y slice capacity  (1024 + 32 halo)
#define SMN    1028      // (y,M) pairs for knots [kbase-1, kbase+1026]

#define LAM   (-0.26794919243112270647f)   // sqrt(3) - 2
#define ACOEF (0.28867513459481288225f)    // 1 / (2*sqrt(3))

__global__ __launch_bounds__(NTHR, 6)
void spline_kernel(const float* __restrict__ x, float* __restrict__ out,
                   int nout, float step) {
    __shared__ float  sy[SYN];
    __shared__ float2 sYM[SMN];

    const int tid = threadIdx.x;
    const int n = W_DIM - 4;
    const int row = blockIdx.y;
    const int kbase = blockIdx.x * TILE_I;

    const float* xr = x + (size_t)row * W_DIM;
    float* outr = out + (size_t)row * nout + kbase * 4;

    const int ilo = (kbase >= 16) ? (kbase - 16) : 0;
    int ihi = kbase + TILE_I + 16; if (ihi > W_DIM) ihi = W_DIM;
    const int NY = ihi - ilo;

    // ---- load y slice (+halo), aligned float4 ----
    {
        const float4* x4 = (const float4*)(xr + ilo);
        float4* sy4 = (float4*)sy;
        for (int v = tid; v < (NY >> 2); v += NTHR) sy4[v] = x4[v];
    }
    __syncthreads();

    // ---- interior M via 17-tap FIR; write (y, M) float2 pairs ----
    {
        const float C0 = -4.3923048f;
        const float C[KT] = { 2.7846097f, -0.7461340f, 0.1999261f, -0.0535701f,
                              0.0143541f, -0.0038462f, 0.0010306f, -0.0002761f };
        int gfirst = kbase - 1; if (gfirst < 20) gfirst = 20;
        int glast = kbase + TILE_I + 1; if (glast > W_DIM - 21) glast = W_DIM - 21;
        const int lstart = ((gfirst - ilo) >> 2) << 2;   // >= 8, 4-aligned
        const int nch = ((glast - ilo - lstart) >> 2) + 1;
        for (int c = tid; c < nch; c += NTHR) {
            const int li0 = lstart + 4 * c;
            float win[20];                       // y[li0-8 .. li0+11]
            const float4* ws = (const float4*)(sy + li0 - 8);
            #pragma unroll
            for (int v = 0; v < 5; ++v) ((float4*)win)[v] = ws[v];
            #pragma unroll
            for (int m = 0; m < 4; ++m) {
                float acc = C0 * win[8 + m];
                #pragma unroll
                for (int k = 1; k <= KT; ++k)
                    acc = fmaf(C[k - 1], win[8 + m - k] + win[8 + m + k], acc);
                const int gi = ilo + li0 + m;
                if (gi >= gfirst && gi <= glast)
                    sYM[gi - kbase + 1] = make_float2(win[8 + m], acc);
            }
        }
    }

    // ---- left edge (row-start tile): exact M[0..19] via Green sums ----
    if (kbase == 0 && tid < 20) {
        const float M1 = sy[2] - 2.f * sy[1] + sy[0];
        float SL = 0.f, lp = LAM;
        #pragma unroll 4
        for (int j = 0; j < 24; ++j) {
            float b = 6.f * (sy[j + 3] - 2.f * sy[j + 2] + sy[j + 1]);
            if (j == 0) b -= M1;
            SL = fmaf(lp, b, SL);
            lp *= LAM;
        }
        float Mv;
        if (tid == 1) {
            Mv = M1;
        } else {
            const int jj = (tid == 0) ? 0 : tid - 2;
            float acc = 0.f, p = 1.f;
            #pragma unroll 4
            for (int d = 0; d <= 12; ++d) {
                const int j = jj - d;
                if (j >= 0) {
                    float b = 6.f * (sy[j + 3] - 2.f * sy[j + 2] + sy[j + 1]);
                    if (j == 0) b -= M1;
                    acc = fmaf(p, b, acc);
                }
                p *= LAM;
            }
            p = LAM;
            #pragma unroll 4
            for (int d = 1; d <= 12; ++d) {
                const int j = jj + d;            // always < n
                float b = 6.f * (sy[j + 3] - 2.f * sy[j + 2] + sy[j + 1]);
                acc = fmaf(p, b, acc);
                p *= LAM;
            }
            float pw = LAM;                      // lam^{jj+1}
            for (int s = 0; s < jj; ++s) pw *= LAM;
            acc -= pw * SL;
            Mv = ACOEF * acc;
            if (tid == 0) Mv = 2.f * M1 - Mv;
        }
        sYM[tid + 1] = make_float2(sy[tid], Mv); // gi = tid (kbase == 0)
    }

    // ---- right edge (row-end tile): exact M[W-20..W-1] ----
    if (kbase + TILE_I == W_DIM && tid >= 32 && tid < 52) {
        const int t = tid - 32;
        const int gi = W_DIM - 20 + t;
        const int lW = W_DIM - ilo;
        const float Mn2 = sy[lW - 1] - 2.f * sy[lW - 2] + sy[lW - 3];
        float SR = 0.f, lp = LAM;
        #pragma unroll 4
        for (int m = 0; m < 24; ++m) {
            const int j = n - 1 - m;
            float b = 6.f * (sy[j + 3 - ilo] - 2.f * sy[j + 2 - ilo] + sy[j + 1 - ilo]);
            if (j == n - 1) b -= Mn2;
            SR = fmaf(lp, b, SR);
            lp *= LAM;
        }
        float Mv;
        if (t == 18) {
            Mv = Mn2;                            // gi == W-2
        } else {
            const int jj = (t == 19) ? (n - 1) : (gi - 2);
            float acc = 0.f, p = 1.f;
            #pragma unroll 4
            for (int d = 0; d <= 12; ++d) {
                const int j = jj - d;            // always >= 0
                float b = 6.f * (sy[j + 3 - ilo] - 2.f * sy[j + 2 - ilo] + sy[j + 1 - ilo]);
                if (j == n - 1) b -= Mn2;
                acc = fmaf(p, b, acc);
                p *= LAM;
            }
            p = LAM;
            #pragma unroll 4
            for (int d = 1; d <= 12; ++d) {
                const int j = jj + d;
                if (j < n) {
                    float b = 6.f * (sy[j + 3 - ilo] - 2.f * sy[j + 2 - ilo] + sy[j + 1 - ilo]);
                    acc = fmaf(p, b, acc);
                }
                p *= LAM;
            }
            float pw = LAM;                      // lam^{n-jj}
            for (int s = 0; s < n - 1 - jj; ++s) pw *= LAM;
            acc -= pw * SR;
            Mv = ACOEF * acc;
            if (t == 19) Mv = 2.f * Mn2 - Mv;
        }
        sYM[gi - kbase + 1] = make_float2(sy[gi - ilo], Mv);
    }
    __syncthreads();

    // ---- evaluate: 4 chunks/thread, 3 LDS.64 + selects + 3 FMA x4 ----
    {
        float4* out4 = (float4*)outr;
        #pragma unroll
        for (int k = 0; k < TILE_I / NTHR; ++k) {
            const int cl = tid + k * NTHR;
            const int cg = kbase + cl;
            const float q0f = (float)(4 * cg);
            const float fq0 = q0f * step;        // == reference xq
            int i0 = (int)fq0;
            if (i0 > W_DIM - 2) i0 = W_DIM - 2;
            const float fi0 = (float)i0;
            const int iL = i0 - kbase + 1;       // in [0, 1025]

            const float2 p0 = sYM[iL];
            const float2 p1 = sYM[iL + 1];
            const float2 p2 = sYM[iL + 2];       // may be stale; select-discarded
            const float y0 = p0.x, m0 = p0.y;
            const float y1 = p1.x, m1 = p1.y;
            const float y2 = p2.x, m2 = p2.y;

            const float Ax = y0;
            const float Ay = fmaf(fmaf(2.f, m0, m1), -(1.f / 6.f), y1 - y0);
            const float Az = 0.5f * m0;
            const float Aw = (m1 - m0) * (1.f / 6.f);
            const float Bx = y1;
            const float By = fmaf(fmaf(2.f, m1, m2), -(1.f / 6.f), y2 - y1);
            const float Bz = 0.5f * m1;
            const float Bw = (m2 - m1) * (1.f / 6.f);
            const bool bval = (i0 < W_DIM - 2);

            float4 r;
            {
                const float u = fq0 - fi0;       // Sterbenz-exact == ref t
                r.x = fmaf(u, fmaf(u, fmaf(u, Aw, Az), Ay), Ax);
            }
            #pragma unroll
            for (int m = 1; m < 4; ++m) {
                const float fq = (q0f + (float)m) * step;
                const float u = fq - fi0;        // in [0, 2), exact
                const bool up = (u >= 1.0f) && bval;
                const float t = up ? (u - 1.0f) : u;
                const float cx = up ? Bx : Ax;
                const float cy = up ? By : Ay;
                const float cz = up ? Bz : Az;
                const float cw = up ? Bw : Aw;
                ((float*)&r)[m] = fmaf(t, fmaf(t, fmaf(t, cw, cz), cy), cx);
            }
            out4[cl] = r;
        }
    }
}

extern "C" void kernel_launch(void* const* d_in, const int* in_sizes, int n_in,
                              void* d_out, int out_size) {
    const float* x = (const float*)d_in[0];
    float* out = (float*)d_out;

    const int B = in_sizes[0] / W_DIM;               // 512
    const int nout = out_size / B;                   // 32768
    const float step = (float)((double)(W_DIM - 1) / (double)(nout - 1));

    dim3 grid(W_DIM / TILE_I, B);                    // 8 x 512 = 4096 CTAs
    spline_kernel<<<grid, NTHR>>>(x, out, nout, step);
}